// round 5
// baseline (speedup 1.0000x reference)
#include <cuda_runtime.h>
#include <math.h>

#define D_MODEL 1024
#define NUM_HEADS 16
#define HEAD_DIM 64
#define SEQ 2048
#define MAX_BS 4096   // B*S for B=2

// Scratch (allocation-free rule: __device__ globals)
__device__ float g_Qp[MAX_BS * D_MODEL];
__device__ float g_Kp[MAX_BS * D_MODEL];
__device__ float g_Vp[MAX_BS * D_MODEL];
__device__ float g_AO[MAX_BS * D_MODEL];

// ----------------------------------------------------------------------------
// GEMM + bias core: C[M, 1024] = A[M, 1024] @ W[1024, 1024] + bias[1024]
// 128x128 block tile, BK=8, 256 threads, 8x8 microtile.
// Double-buffered smem: one __syncthreads per k-step; next-step global loads
// issued before current-step compute (latency hidden under 512 FFMAs).
// ----------------------------------------------------------------------------
__device__ __forceinline__ void gemm_bias_core(
    const float* __restrict__ A, const float* __restrict__ W,
    const float* __restrict__ bias, float* __restrict__ C)
{
    __shared__ float As[2][8][132];   // [buf][k][m], padded
    __shared__ float Bs[2][8][128];   // [buf][k][n]

    const int tid = threadIdx.x;
    const int tx = tid & 15;       // n microtile
    const int ty = tid >> 4;       // m microtile
    const int mbase = blockIdx.y * 128;
    const int nbase = blockIdx.x * 128;

    const int aRow = tid >> 1;
    const int aCol = (tid & 1) * 4;
    const int bRow = tid >> 5;
    const int bCol = (tid & 31) * 4;

    const float* Aptr = A + (size_t)(mbase + aRow) * D_MODEL + aCol;
    const float* Wptr = W + (size_t)bRow * D_MODEL + nbase + bCol;

    float acc[8][8];
#pragma unroll
    for (int i = 0; i < 8; i++)
#pragma unroll
        for (int j = 0; j < 8; j++) acc[i][j] = 0.0f;

    // Preload tile 0 into buffer 0
    {
        float4 av = *(const float4*)(Aptr);
        float4 bv = *(const float4*)(Wptr);
        As[0][aCol + 0][aRow] = av.x;
        As[0][aCol + 1][aRow] = av.y;
        As[0][aCol + 2][aRow] = av.z;
        As[0][aCol + 3][aRow] = av.w;
        *(float4*)&Bs[0][bRow][bCol] = bv;
    }
    __syncthreads();

    int cur = 0;
    const int NSTEP = D_MODEL / 8;
    for (int step = 0; step < NSTEP; step++) {
        float4 av, bv;
        const bool has_next = (step + 1) < NSTEP;
        if (has_next) {
            const int k0 = (step + 1) * 8;
            av = *(const float4*)(Aptr + k0);
            bv = *(const float4*)(Wptr + (size_t)k0 * D_MODEL);
        }

#pragma unroll
        for (int kk = 0; kk < 8; kk++) {
            float a[8], b[8];
            *(float4*)(a)     = *(const float4*)&As[cur][kk][ty * 8];
            *(float4*)(a + 4) = *(const float4*)&As[cur][kk][ty * 8 + 4];
            *(float4*)(b)     = *(const float4*)&Bs[cur][kk][tx * 8];
            *(float4*)(b + 4) = *(const float4*)&Bs[cur][kk][tx * 8 + 4];
#pragma unroll
            for (int i = 0; i < 8; i++)
#pragma unroll
                for (int j = 0; j < 8; j++)
                    acc[i][j] += a[i] * b[j];
        }

        if (has_next) {
            const int nxt = cur ^ 1;
            As[nxt][aCol + 0][aRow] = av.x;
            As[nxt][aCol + 1][aRow] = av.y;
            As[nxt][aCol + 2][aRow] = av.z;
            As[nxt][aCol + 3][aRow] = av.w;
            *(float4*)&Bs[nxt][bRow][bCol] = bv;
            __syncthreads();
            cur = nxt;
        }
    }

    // Epilogue: bias is row-invariant -> load once, reuse for all 8 rows.
    float bv8[8];
    *(float4*)(bv8)     = *(const float4*)&bias[nbase + tx * 8];
    *(float4*)(bv8 + 4) = *(const float4*)&bias[nbase + tx * 8 + 4];
#pragma unroll
    for (int i = 0; i < 8; i++) {
        const int m = mbase + ty * 8 + i;
#pragma unroll
        for (int j = 0; j < 8; j += 4) {
            const int n = nbase + tx * 8 + j;
            float4 o;
            o.x = acc[i][j + 0] + bv8[j + 0];
            o.y = acc[i][j + 1] + bv8[j + 1];
            o.z = acc[i][j + 2] + bv8[j + 2];
            o.w = acc[i][j + 3] + bv8[j + 3];
            *(float4*)&C[(size_t)m * D_MODEL + n] = o;
        }
    }
}

// Fused Q/K/V projection: gridDim.z selects which of the three GEMMs this CTA
// computes. One launch -> one scheduling tail instead of three.
__global__ __launch_bounds__(256) void qkv_gemm_kernel(
    const float* __restrict__ q, const float* __restrict__ k,
    const float* __restrict__ v,
    const float* __restrict__ w_q, const float* __restrict__ b_q,
    const float* __restrict__ w_k, const float* __restrict__ b_k,
    const float* __restrict__ w_v, const float* __restrict__ b_v,
    float* __restrict__ Qp, float* __restrict__ Kp, float* __restrict__ Vp)
{
    const int z = blockIdx.z;
    const float* A    = (z == 0) ? q   : (z == 1) ? k   : v;
    const float* W    = (z == 0) ? w_q : (z == 1) ? w_k : w_v;
    const float* bias = (z == 0) ? b_q : (z == 1) ? b_k : b_v;
    float*       C    = (z == 0) ? Qp  : (z == 1) ? Kp  : Vp;
    gemm_bias_core(A, W, bias, C);
}

// Single GEMM (O-projection)
__global__ __launch_bounds__(256) void gemm_bias_kernel(
    const float* __restrict__ A, const float* __restrict__ W,
    const float* __restrict__ bias, float* __restrict__ C)
{
    gemm_bias_core(A, W, bias, C);
}

// ----------------------------------------------------------------------------
// Flash attention, fp32, Dh=64. One CTA = one (b, h, 64-row query tile).
// 256 threads; 16x16 thread grid; 4x4 microtiles for S=QK^T and O=PV.
// smem: Qs [d][i], KPs [d][j] (reused as Ps [i][j]), Vs [j][d]. 48 KB.
// K/V global loads for iteration t+1 are issued right after S-compute of
// iteration t and land in registers; LDG latency is hidden under softmax+PV.
// ----------------------------------------------------------------------------
__global__ __launch_bounds__(256) void flash_attn_kernel(
    const float* __restrict__ Qg, const float* __restrict__ Kg,
    const float* __restrict__ Vg, float* __restrict__ Og)
{
    __shared__ float Qs[64 * 64];   // [d][i]
    __shared__ float KPs[64 * 64];  // phase 1: K as [d][j]; phase 2: P as [i][j]
    __shared__ float Vs[64 * 64];   // [j][d]

    const int qt = blockIdx.x;
    const int h  = blockIdx.y;
    const int b  = blockIdx.z;
    const int tid = threadIdx.x;
    const int tx = tid & 15;        // key / d-out microtile
    const int ty = tid >> 4;        // query-row microtile

    const size_t base = ((size_t)b * SEQ) * D_MODEL + (size_t)h * HEAD_DIM;
    const int qbase = qt * 64;

    const int kj  = tid & 63;
    const int kd0 = (tid >> 6) * 4;
    const float* Kbase = Kg + base;
    const float* Vbase = Vg + base;

    // Load Q tile, transposed to [d][i], pre-scaled by 1/sqrt(Dh)
    {
        const int i  = tid & 63;
        const int d0 = (tid >> 6) * 4;
        const float* qp = Qg + base + (size_t)(qbase + i) * D_MODEL;
#pragma unroll
        for (int r = 0; r < 4; r++) {
            const int d = d0 + r * 16;
            float4 vv = *(const float4*)(qp + d);
            Qs[(d + 0) * 64 + i] = vv.x * 0.125f;
            Qs[(d + 1) * 64 + i] = vv.y * 0.125f;
            Qs[(d + 2) * 64 + i] = vv.z * 0.125f;
            Qs[(d + 3) * 64 + i] = vv.w * 0.125f;
        }
    }

    float acc[4][4];
    float mrow[4], lrow[4];
#pragma unroll
    for (int r = 0; r < 4; r++) {
        mrow[r] = -1e30f;
        lrow[r] = 0.0f;
#pragma unroll
        for (int c = 0; c < 4; c++) acc[r][c] = 0.0f;
    }

    // Prefetch registers for tile 0
    float4 kreg[4], vreg[4];
    {
        const float* kp = Kbase + (size_t)kj * D_MODEL;
#pragma unroll
        for (int r = 0; r < 4; r++)
            kreg[r] = *(const float4*)(kp + kd0 + r * 16);
#pragma unroll
        for (int it = 0; it < 4; it++) {
            const int s  = tid + it * 256;
            const int j2 = s >> 4;
            const int d4 = (s & 15) * 4;
            vreg[it] = *(const float4*)(Vbase + (size_t)j2 * D_MODEL + d4);
        }
    }

    const int NKV = SEQ / 64;
    for (int kvt = 0; kvt < NKV; kvt++) {
        __syncthreads();   // prior-iteration Ps/Vs reads complete

        // Store prefetched K tile (transposed) and V tile (natural) to smem
#pragma unroll
        for (int r = 0; r < 4; r++) {
            const int d = kd0 + r * 16;
            KPs[(d + 0) * 64 + kj] = kreg[r].x;
            KPs[(d + 1) * 64 + kj] = kreg[r].y;
            KPs[(d + 2) * 64 + kj] = kreg[r].z;
            KPs[(d + 3) * 64 + kj] = kreg[r].w;
        }
#pragma unroll
        for (int it = 0; it < 4; it++) {
            const int s  = tid + it * 256;
            const int j2 = s >> 4;
            const int d4 = (s & 15) * 4;
            *(float4*)&Vs[j2 * 64 + d4] = vreg[it];
        }
        __syncthreads();

        // S tile = Q K^T (scaled): rows ty*4+r, keys tx*4+c
        float sc[4][4];
#pragma unroll
        for (int r = 0; r < 4; r++)
#pragma unroll
            for (int c = 0; c < 4; c++) sc[r][c] = 0.0f;

#pragma unroll 16
        for (int d = 0; d < 64; d++) {
            float4 q4 = *(const float4*)&Qs[d * 64 + ty * 4];
            float4 k4 = *(const float4*)&KPs[d * 64 + tx * 4];
            const float qa[4] = {q4.x, q4.y, q4.z, q4.w};
            const float ka[4] = {k4.x, k4.y, k4.z, k4.w};
#pragma unroll
            for (int r = 0; r < 4; r++)
#pragma unroll
                for (int c = 0; c < 4; c++)
                    sc[r][c] += qa[r] * ka[c];
        }

        // Issue next tile's global loads now; latency hides under softmax+PV.
        if (kvt + 1 < NKV) {
            const int kb = (kvt + 1) * 64;
            const float* kp = Kbase + (size_t)(kb + kj) * D_MODEL;
#pragma unroll
            for (int r = 0; r < 4; r++)
                kreg[r] = *(const float4*)(kp + kd0 + r * 16);
#pragma unroll
            for (int it = 0; it < 4; it++) {
                const int s  = tid + it * 256;
                const int j2 = s >> 4;
                const int d4 = (s & 15) * 4;
                vreg[it] = *(const float4*)(Vbase + (size_t)(kb + j2) * D_MODEL + d4);
            }
        }
        __syncthreads();   // K reads finished before overwriting KPs with P

        // Online softmax per row; write P into KPs as [i][j]
#pragma unroll
        for (int r = 0; r < 4; r++) {
            float mx = fmaxf(fmaxf(sc[r][0], sc[r][1]), fmaxf(sc[r][2], sc[r][3]));
            mx = fmaxf(mx, __shfl_xor_sync(0xffffffffu, mx, 1));
            mx = fmaxf(mx, __shfl_xor_sync(0xffffffffu, mx, 2));
            mx = fmaxf(mx, __shfl_xor_sync(0xffffffffu, mx, 4));
            mx = fmaxf(mx, __shfl_xor_sync(0xffffffffu, mx, 8));
            const float mn = fmaxf(mrow[r], mx);
            const float corr = __expf(mrow[r] - mn);
            float p0 = __expf(sc[r][0] - mn);
            float p1 = __expf(sc[r][1] - mn);
            float p2 = __expf(sc[r][2] - mn);
            float p3 = __expf(sc[r][3] - mn);
            float sum = p0 + p1 + p2 + p3;
            sum += __shfl_xor_sync(0xffffffffu, sum, 1);
            sum += __shfl_xor_sync(0xffffffffu, sum, 2);
            sum += __shfl_xor_sync(0xffffffffu, sum, 4);
            sum += __shfl_xor_sync(0xffffffffu, sum, 8);
            lrow[r] = lrow[r] * corr + sum;
            mrow[r] = mn;
#pragma unroll
            for (int c = 0; c < 4; c++) acc[r][c] *= corr;
            *(float4*)&KPs[(ty * 4 + r) * 64 + tx * 4] = make_float4(p0, p1, p2, p3);
        }
        __syncthreads();

        // O += P V : rows ty*4+r, dims tx*4+c
#pragma unroll 8
        for (int j = 0; j < 64; j++) {
            float4 v4 = *(const float4*)&Vs[j * 64 + tx * 4];
#pragma unroll
            for (int r = 0; r < 4; r++) {
                const float pv = KPs[(ty * 4 + r) * 64 + j];   // broadcast load
                acc[r][0] += pv * v4.x;
                acc[r][1] += pv * v4.y;
                acc[r][2] += pv * v4.z;
                acc[r][3] += pv * v4.w;
            }
        }
    }

    // Epilogue: normalize and store
#pragma unroll
    for (int r = 0; r < 4; r++) {
        const float inv = 1.0f / lrow[r];
        float4 o;
        o.x = acc[r][0] * inv;
        o.y = acc[r][1] * inv;
        o.z = acc[r][2] * inv;
        o.w = acc[r][3] * inv;
        *(float4*)(Og + base + (size_t)(qbase + ty * 4 + r) * D_MODEL + tx * 4) = o;
    }
}

// ----------------------------------------------------------------------------
// Launch
// ----------------------------------------------------------------------------
extern "C" void kernel_launch(void* const* d_in, const int* in_sizes, int n_in,
                              void* d_out, int out_size)
{
    const float* q   = (const float*)d_in[0];
    const float* k   = (const float*)d_in[1];
    const float* v   = (const float*)d_in[2];
    const float* w_q = (const float*)d_in[3];
    const float* b_q = (const float*)d_in[4];
    const float* w_k = (const float*)d_in[5];
    const float* b_k = (const float*)d_in[6];
    const float* w_v = (const float*)d_in[7];
    const float* b_v = (const float*)d_in[8];
    const float* w_o = (const float*)d_in[9];
    const float* b_o = (const float*)d_in[10];
    float* out = (float*)d_out;

    const int BS = in_sizes[0] / D_MODEL;   // B * S
    const int B  = BS / SEQ;

    float *Qp, *Kp, *Vp, *AO;
    cudaGetSymbolAddress((void**)&Qp, g_Qp);
    cudaGetSymbolAddress((void**)&Kp, g_Kp);
    cudaGetSymbolAddress((void**)&Vp, g_Vp);
    cudaGetSymbolAddress((void**)&AO, g_AO);

    dim3 qkv_grid(D_MODEL / 128, BS / 128, 3);
    qkv_gemm_kernel<<<qkv_grid, 256>>>(q, k, v, w_q, b_q, w_k, b_k, w_v, b_v,
                                       Qp, Kp, Vp);

    dim3 attn_grid(SEQ / 64, NUM_HEADS, B);
    flash_attn_kernel<<<attn_grid, 256>>>(Qp, Kp, Vp, AO);

    dim3 gemm_grid(D_MODEL / 128, BS / 128);
    gemm_bias_kernel<<<gemm_grid, 256>>>(AO, w_o, b_o, out);
}